// round 5
// baseline (speedup 1.0000x reference)
#include <cuda_runtime.h>
#include <math.h>

#define T_  4
#define C_  512
#define H_  192
#define W_  192
#define HW_ (H_ * W_)
#define CHW_ ((size_t)C_ * HW_)
#define W4_ (W_ / 4)
#define W8_ (W_ / 8)

struct TCoef { float ax, bx, cx, ay, by, cy; };
struct TInt  { int kx, ky; float fx, fy; };

__device__ float g_part[C_ * 4];
__device__ TCoef g_tc[T_];
__device__ TInt  g_ti[T_];
__device__ int   g_fast;

// ---------------------------------------------------------------------------
// Kernel 1: GAP, 4 partial blocks per channel (proven 14.6us @66% DRAM)
// ---------------------------------------------------------------------------
__global__ void __launch_bounds__(256) gap_kernel(const float* __restrict__ F) {
    int c = blockIdx.x >> 2;
    int q = blockIdx.x & 3;
    const int n4q = HW_ / 16;   // 2304 float4 per quarter
    const float4* p = reinterpret_cast<const float4*>(F + (size_t)c * HW_) + q * n4q;
    float s = 0.f;
    #pragma unroll
    for (int i = 0; i < 9; ++i) {
        float4 v = p[i * 256 + threadIdx.x];
        s += (v.x + v.y) + (v.z + v.w);
    }
    #pragma unroll
    for (int o = 16; o > 0; o >>= 1) s += __shfl_xor_sync(0xffffffffu, s, o);
    __shared__ float sh[8];
    if ((threadIdx.x & 31) == 0) sh[threadIdx.x >> 5] = s;
    __syncthreads();
    if (threadIdx.x == 0) {
        float t = 0.f;
        #pragma unroll
        for (int i = 0; i < 8; ++i) t += sh[i];
        g_part[c * 4 + q] = t;
    }
}

// ---------------------------------------------------------------------------
// Kernel 2: theta
// ---------------------------------------------------------------------------
__global__ void theta_kernel(const float* __restrict__ w1,
                             const float* __restrict__ b1,
                             const float* __restrict__ a,
                             float* __restrict__ out_tail) {
    int warp = threadIdx.x >> 5;
    int lane = threadIdx.x & 31;

    float s = 0.f;
    for (int k = lane; k < C_; k += 32) {
        float4 pp = *reinterpret_cast<const float4*>(&g_part[4 * k]);
        s += ((pp.x + pp.y) + (pp.z + pp.w)) * w1[warp * C_ + k];
    }
    #pragma unroll
    for (int o = 16; o > 0; o >>= 1) s += __shfl_xor_sync(0xffffffffu, s, o);

    __shared__ float Bs[2 * T_];
    if (lane == 0) Bs[warp] = tanhf(s * (1.0f / (float)HW_) + b1[warp]);
    __syncthreads();

    float a00 = a[0], a01 = a[1], a10 = a[2], a11 = a[3];

    if (threadIdx.x == 0)
        g_fast = (a00 == 1.0f && a01 == 0.0f && a10 == 0.0f && a11 == 1.0f) ? 1 : 0;

    if (threadIdx.x < T_) {
        int t = threadIdx.x;
        float bx = Bs[2 * t + 0];
        float by = Bs[2 * t + 1];
        TCoef tc;
        tc.ax = a00;
        tc.bx = a01 * ((float)W_ / (float)H_);
        tc.cx = 0.5f * (a00 - a00 * (float)W_ + a01 * ((float)W_ / (float)H_)
                        - a01 * (float)W_ + bx * (float)W_ + (float)W_ - 1.0f);
        tc.ay = a10 * ((float)H_ / (float)W_);
        tc.by = a11;
        tc.cy = 0.5f * (a10 * ((float)H_ / (float)W_) - a10 * (float)H_ + a11
                        - a11 * (float)H_ + by * (float)H_ + (float)H_ - 1.0f);
        g_tc[t] = tc;

        TInt ti;
        float kxf = floorf(tc.cx), kyf = floorf(tc.cy);
        ti.kx = (int)kxf;  ti.fx = tc.cx - kxf;
        ti.ky = (int)kyf;  ti.fy = tc.cy - kyf;
        g_ti[t] = ti;
    }

    if (threadIdx.x < T_ * 4) out_tail[threadIdx.x] = a[threadIdx.x & 3];
    if (threadIdx.x < 2 * T_) out_tail[T_ * 4 + threadIdx.x] = Bs[threadIdx.x];
}

// ---------------------------------------------------------------------------
// Kernel 3: bilinear warp, 8 outputs/thread/t. Fast path: 3 aligned
// predicated LDG.128 per source row, per-float4 OOB masking (W%4==0 so a
// source col is OOB iff its whole float4 is OOB), uniform phase select,
// plain STG.128 (no stcs, no shuffles).
// ---------------------------------------------------------------------------
__global__ void __launch_bounds__(256) sample_kernel(const float* __restrict__ F,
                                                     float* __restrict__ out) {
    int idx = blockIdx.x * 256 + threadIdx.x;
    int w8 = idx % W8_;                 // 24 per row
    int t2 = idx / W8_;
    int h  = t2 % H_;
    int c  = t2 / H_;
    int w0 = w8 * 8;

    const float* Fc = F + (size_t)c * HW_;
    float* outp = out + (size_t)c * HW_ + (size_t)h * W_ + w0;

    if (g_fast) {
        #pragma unroll
        for (int t = 0; t < T_; ++t) {
            TInt ti = g_ti[t];
            int y0 = h + ti.ky;
            bool vy0 = (unsigned)y0       < (unsigned)H_;
            bool vy1 = (unsigned)(y0 + 1) < (unsigned)H_;
            int s  = ti.kx & 3;                       // uniform across grid
            int base4 = 2 * w8 + ((ti.kx - s) >> 2);  // aligned float4 idx (exact)

            const float4* r0p = reinterpret_cast<const float4*>(
                Fc + (size_t)(vy0 ? y0 : 0) * W_);
            const float4* r1p = reinterpret_cast<const float4*>(
                Fc + (size_t)(vy1 ? (y0 + 1) : 0) * W_);

            bool k0 = (unsigned)(base4 + 0) < (unsigned)W4_;
            bool k1 = (unsigned)(base4 + 1) < (unsigned)W4_;
            bool k2 = (unsigned)(base4 + 2) < (unsigned)W4_;

            const float4 z = make_float4(0.f, 0.f, 0.f, 0.f);
            float4 A0 = (k0 && vy0) ? __ldg(&r0p[base4 + 0]) : z;
            float4 A1 = (k1 && vy0) ? __ldg(&r0p[base4 + 1]) : z;
            float4 A2 = (k2 && vy0) ? __ldg(&r0p[base4 + 2]) : z;
            float4 B0 = (k0 && vy1) ? __ldg(&r1p[base4 + 0]) : z;
            float4 B1 = (k1 && vy1) ? __ldg(&r1p[base4 + 1]) : z;
            float4 B2 = (k2 && vy1) ? __ldg(&r1p[base4 + 2]) : z;

            float fy = ti.fy;
            float m0  = A0.x + fy * (B0.x - A0.x);
            float m1  = A0.y + fy * (B0.y - A0.y);
            float m2  = A0.z + fy * (B0.z - A0.z);
            float m3  = A0.w + fy * (B0.w - A0.w);
            float m4  = A1.x + fy * (B1.x - A1.x);
            float m5  = A1.y + fy * (B1.y - A1.y);
            float m6  = A1.z + fy * (B1.z - A1.z);
            float m7  = A1.w + fy * (B1.w - A1.w);
            float m8  = A2.x + fy * (B2.x - A2.x);
            float m9  = A2.y + fy * (B2.y - A2.y);
            float m10 = A2.z + fy * (B2.z - A2.z);
            float m11 = A2.w + fy * (B2.w - A2.w);

            float fx = ti.fx;
            float4 o0, o1;
            #define MIX_(e0, e1) ((e0) + fx * ((e1) - (e0)))
            switch (s) {   // uniform branch across the grid
                case 0:
                    o0.x=MIX_(m0,m1); o0.y=MIX_(m1,m2); o0.z=MIX_(m2,m3); o0.w=MIX_(m3,m4);
                    o1.x=MIX_(m4,m5); o1.y=MIX_(m5,m6); o1.z=MIX_(m6,m7); o1.w=MIX_(m7,m8);
                    break;
                case 1:
                    o0.x=MIX_(m1,m2); o0.y=MIX_(m2,m3); o0.z=MIX_(m3,m4); o0.w=MIX_(m4,m5);
                    o1.x=MIX_(m5,m6); o1.y=MIX_(m6,m7); o1.z=MIX_(m7,m8); o1.w=MIX_(m8,m9);
                    break;
                case 2:
                    o0.x=MIX_(m2,m3); o0.y=MIX_(m3,m4); o0.z=MIX_(m4,m5); o0.w=MIX_(m5,m6);
                    o1.x=MIX_(m6,m7); o1.y=MIX_(m7,m8); o1.z=MIX_(m8,m9); o1.w=MIX_(m9,m10);
                    break;
                default:
                    o0.x=MIX_(m3,m4); o0.y=MIX_(m4,m5); o0.z=MIX_(m5,m6); o0.w=MIX_(m6,m7);
                    o1.x=MIX_(m7,m8); o1.y=MIX_(m8,m9); o1.z=MIX_(m9,m10); o1.w=MIX_(m10,m11);
                    break;
            }
            #undef MIX_
            float* po = outp + (size_t)t * CHW_;
            *reinterpret_cast<float4*>(po)     = o0;
            *reinterpret_cast<float4*>(po + 4) = o1;
        }
    } else {
        // General affine fallback (scalar gathers), 8-wide
        #pragma unroll
        for (int t = 0; t < T_; ++t) {
            TCoef tc = g_tc[t];
            float bases_x = tc.bx * (float)h + tc.cx;
            float bases_y = tc.by * (float)h + tc.cy;
            float vals[8];
            #pragma unroll
            for (int j = 0; j < 8; ++j) {
                float wf = (float)(w0 + j);
                float ix = tc.ax * wf + bases_x;
                float iy = tc.ay * wf + bases_y;
                float ix0f = floorf(ix), iy0f = floorf(iy);
                float fx = ix - ix0f,   fy = iy - iy0f;
                int x0 = (int)ix0f, y0 = (int)iy0f;
                int x1 = x0 + 1,    y1 = y0 + 1;
                bool vx0 = (unsigned)x0 < (unsigned)W_;
                bool vx1 = (unsigned)x1 < (unsigned)W_;
                bool vy0 = (unsigned)y0 < (unsigned)H_;
                bool vy1 = (unsigned)y1 < (unsigned)H_;
                const float* r0 = Fc + (size_t)(vy0 ? y0 : 0) * W_;
                const float* r1 = Fc + (size_t)(vy1 ? y1 : 0) * W_;
                float v00 = (vy0 && vx0) ? __ldg(r0 + x0) : 0.f;
                float v01 = (vy0 && vx1) ? __ldg(r0 + x1) : 0.f;
                float v10 = (vy1 && vx0) ? __ldg(r1 + x0) : 0.f;
                float v11 = (vy1 && vx1) ? __ldg(r1 + x1) : 0.f;
                float wx0 = 1.f - fx, wx1 = fx;
                float wy0 = 1.f - fy, wy1 = fy;
                vals[j] = wy0 * (wx0 * v00 + wx1 * v01) + wy1 * (wx0 * v10 + wx1 * v11);
            }
            float* po = outp + (size_t)t * CHW_;
            *reinterpret_cast<float4*>(po)     = make_float4(vals[0], vals[1], vals[2], vals[3]);
            *reinterpret_cast<float4*>(po + 4) = make_float4(vals[4], vals[5], vals[6], vals[7]);
        }
    }
}

// ---------------------------------------------------------------------------
extern "C" void kernel_launch(void* const* d_in, const int* in_sizes, int n_in,
                              void* d_out, int out_size) {
    const float* F  = (const float*)d_in[0];
    const float* w1 = (const float*)d_in[1];
    const float* b1 = (const float*)d_in[2];
    const float* a  = (const float*)d_in[3];
    float* out = (float*)d_out;

    float* out_tail = out + (size_t)T_ * CHW_;

    gap_kernel<<<C_ * 4, 256>>>(F);
    theta_kernel<<<1, 256>>>(w1, b1, a, out_tail);

    const int total = C_ * H_ * W8_;     // 2,359,296 threads
    sample_kernel<<<total / 256, 256>>>(F, out);
}

// round 6
// speedup vs baseline: 1.1338x; 1.1338x over previous
#include <cuda_runtime.h>
#include <math.h>

#define T_  4
#define C_  512
#define H_  192
#define W_  192
#define HW_ (H_ * W_)
#define CHW_ ((size_t)C_ * HW_)
#define W4_ (W_ / 4)

// General-affine coefficients: ix = ax*w + bx*h + cx ; iy = ay*w + by*h + cy
struct TCoef { float ax, bx, cx, ay, by, cy; };
// Translation fast-path: ix = w + (kx + fx), iy = h + (ky + fy)
struct TInt  { int kx, ky; float fx, fy; };

__device__ float g_part[C_ * 4];   // 4 partial sums per channel
__device__ TCoef g_tc[T_];
__device__ TInt  g_ti[T_];
__device__ int   g_fast;

// ---------------------------------------------------------------------------
// Kernel 1: global average pool, 4 blocks per channel (partial sums)
// ---------------------------------------------------------------------------
__global__ void gap_kernel(const float* __restrict__ F) {
    int c = blockIdx.x >> 2;
    int q = blockIdx.x & 3;
    const int n4q = HW_ / 16;   // 2304 float4 per quarter
    const float4* p = reinterpret_cast<const float4*>(F + (size_t)c * HW_) + q * n4q;
    float s = 0.f;
    #pragma unroll
    for (int i = 0; i < 9; ++i) {           // 9 * 256 = 2304
        float4 v = p[i * 256 + threadIdx.x];
        s += (v.x + v.y) + (v.z + v.w);
    }
    #pragma unroll
    for (int o = 16; o > 0; o >>= 1) s += __shfl_xor_sync(0xffffffffu, s, o);
    __shared__ float sh[8];
    if ((threadIdx.x & 31) == 0) sh[threadIdx.x >> 5] = s;
    __syncthreads();
    if (threadIdx.x == 0) {
        float t = 0.f;
        #pragma unroll
        for (int i = 0; i < 8; ++i) t += sh[i];
        g_part[c * 4 + q] = t;
    }
}

// ---------------------------------------------------------------------------
// Kernel 2: B = tanh(g @ w1.T + b1); derive coefficients; write output tail
// ---------------------------------------------------------------------------
__global__ void theta_kernel(const float* __restrict__ w1,
                             const float* __restrict__ b1,
                             const float* __restrict__ a,
                             float* __restrict__ out_tail) {
    int warp = threadIdx.x >> 5;
    int lane = threadIdx.x & 31;

    float s = 0.f;
    for (int k = lane; k < C_; k += 32) {
        float4 pp = *reinterpret_cast<const float4*>(&g_part[4 * k]);
        s += ((pp.x + pp.y) + (pp.z + pp.w)) * w1[warp * C_ + k];
    }
    #pragma unroll
    for (int o = 16; o > 0; o >>= 1) s += __shfl_xor_sync(0xffffffffu, s, o);

    __shared__ float Bs[2 * T_];
    if (lane == 0) Bs[warp] = tanhf(s * (1.0f / (float)HW_) + b1[warp]);
    __syncthreads();

    float a00 = a[0], a01 = a[1], a10 = a[2], a11 = a[3];

    if (threadIdx.x == 0) {
        g_fast = (a00 == 1.0f && a01 == 0.0f && a10 == 0.0f && a11 == 1.0f) ? 1 : 0;
    }

    if (threadIdx.x < T_) {
        int t = threadIdx.x;
        float bx = Bs[2 * t + 0];
        float by = Bs[2 * t + 1];
        TCoef tc;
        tc.ax = a00;
        tc.bx = a01 * ((float)W_ / (float)H_);
        tc.cx = 0.5f * (a00 - a00 * (float)W_ + a01 * ((float)W_ / (float)H_)
                        - a01 * (float)W_ + bx * (float)W_ + (float)W_ - 1.0f);
        tc.ay = a10 * ((float)H_ / (float)W_);
        tc.by = a11;
        tc.cy = 0.5f * (a10 * ((float)H_ / (float)W_) - a10 * (float)H_ + a11
                        - a11 * (float)H_ + by * (float)H_ + (float)H_ - 1.0f);
        g_tc[t] = tc;

        // Fast-path integers (valid when affine part is identity: ix = w + cx)
        TInt ti;
        float kxf = floorf(tc.cx), kyf = floorf(tc.cy);
        ti.kx = (int)kxf;  ti.fx = tc.cx - kxf;
        ti.ky = (int)kyf;  ti.fy = tc.cy - kyf;
        g_ti[t] = ti;
    }

    if (threadIdx.x < T_ * 4) out_tail[threadIdx.x] = a[threadIdx.x & 3];
    if (threadIdx.x < 2 * T_) out_tail[T_ * 4 + threadIdx.x] = Bs[threadIdx.x];
}

// ---------------------------------------------------------------------------
// Kernel 3: bilinear warp (R2 layout). Fast path: two aligned LDG.128 per
// source row + uniform-phase register select. ONLY change vs R2: __stcs
// streaming stores so the 302MB output stream doesn't evict F from L2.
// ---------------------------------------------------------------------------
__global__ void sample_kernel(const float* __restrict__ F,
                              float* __restrict__ out) {
    int idx = blockIdx.x * blockDim.x + threadIdx.x;
    int w4 = idx % W4_;
    int t2 = idx / W4_;
    int h  = t2 % H_;
    int c  = t2 / H_;
    if (c >= C_) return;
    int w0 = w4 * 4;

    const float* Fc = F + (size_t)c * HW_;
    float* outp = out + (size_t)c * HW_ + (size_t)h * W_ + w0;

    if (g_fast) {
        #pragma unroll
        for (int t = 0; t < T_; ++t) {
            TInt ti = g_ti[t];
            int y0 = h + ti.ky;
            bool vy0 = (unsigned)y0 < (unsigned)H_;
            bool vy1 = (unsigned)(y0 + 1) < (unsigned)H_;
            int x0 = w0 + ti.kx;
            int s  = ti.kx & 3;                 // uniform across grid
            int base4 = (x0 - s) >> 2;          // aligned float4 index
            int b0 = min(max(base4, 0), W4_ - 1);
            int b1 = min(max(base4 + 1, 0), W4_ - 1);

            const float4* r0p = reinterpret_cast<const float4*>(
                Fc + (size_t)(vy0 ? y0 : 0) * W_);
            const float4* r1p = reinterpret_cast<const float4*>(
                Fc + (size_t)(vy1 ? (y0 + 1) : 0) * W_);

            float4 A0 = __ldg(&r0p[b0]);
            float4 A1 = __ldg(&r0p[b1]);
            float4 B0 = __ldg(&r1p[b0]);
            float4 B1 = __ldg(&r1p[b1]);
            if (!vy0) { A0 = make_float4(0,0,0,0); A1 = make_float4(0,0,0,0); }
            if (!vy1) { B0 = make_float4(0,0,0,0); B1 = make_float4(0,0,0,0); }

            float fy = ti.fy;
            float m0 = A0.x + fy * (B0.x - A0.x);
            float m1 = A0.y + fy * (B0.y - A0.y);
            float m2 = A0.z + fy * (B0.z - A0.z);
            float m3 = A0.w + fy * (B0.w - A0.w);
            float m4 = A1.x + fy * (B1.x - A1.x);
            float m5 = A1.y + fy * (B1.y - A1.y);
            float m6 = A1.z + fy * (B1.z - A1.z);
            float m7 = A1.w + fy * (B1.w - A1.w);

            // zero logically-out-of-range columns (true column of slot i is 4*base4+i)
            int xb = 4 * base4;
            if ((unsigned)(xb + 0) >= (unsigned)W_) m0 = 0.f;
            if ((unsigned)(xb + 1) >= (unsigned)W_) m1 = 0.f;
            if ((unsigned)(xb + 2) >= (unsigned)W_) m2 = 0.f;
            if ((unsigned)(xb + 3) >= (unsigned)W_) m3 = 0.f;
            if ((unsigned)(xb + 4) >= (unsigned)W_) m4 = 0.f;
            if ((unsigned)(xb + 5) >= (unsigned)W_) m5 = 0.f;
            if ((unsigned)(xb + 6) >= (unsigned)W_) m6 = 0.f;
            if ((unsigned)(xb + 7) >= (unsigned)W_) m7 = 0.f;

            float fx = ti.fx;
            float4 o;
            #define MIX_(e0, e1) ((e0) + fx * ((e1) - (e0)))
            switch (s) {   // uniform branch: all warps take the same case
                case 0: o.x=MIX_(m0,m1); o.y=MIX_(m1,m2); o.z=MIX_(m2,m3); o.w=MIX_(m3,m4); break;
                case 1: o.x=MIX_(m1,m2); o.y=MIX_(m2,m3); o.z=MIX_(m3,m4); o.w=MIX_(m4,m5); break;
                case 2: o.x=MIX_(m2,m3); o.y=MIX_(m3,m4); o.z=MIX_(m4,m5); o.w=MIX_(m5,m6); break;
                default:o.x=MIX_(m3,m4); o.y=MIX_(m4,m5); o.z=MIX_(m5,m6); o.w=MIX_(m6,m7); break;
            }
            #undef MIX_
            __stcs(reinterpret_cast<float4*>(outp + (size_t)t * CHW_), o);
        }
    } else {
        // General affine fallback (scalar gathers)
        #pragma unroll
        for (int t = 0; t < T_; ++t) {
            TCoef tc = g_tc[t];
            float bases_x = tc.bx * (float)h + tc.cx;
            float bases_y = tc.by * (float)h + tc.cy;
            float4 o;
            float* op = reinterpret_cast<float*>(&o);
            #pragma unroll
            for (int j = 0; j < 4; ++j) {
                float wf = (float)(w0 + j);
                float ix = tc.ax * wf + bases_x;
                float iy = tc.ay * wf + bases_y;
                float ix0f = floorf(ix), iy0f = floorf(iy);
                float fx = ix - ix0f,   fy = iy - iy0f;
                int x0 = (int)ix0f, y0 = (int)iy0f;
                int x1 = x0 + 1,    y1 = y0 + 1;
                bool vx0 = (unsigned)x0 < (unsigned)W_;
                bool vx1 = (unsigned)x1 < (unsigned)W_;
                bool vy0 = (unsigned)y0 < (unsigned)H_;
                bool vy1 = (unsigned)y1 < (unsigned)H_;
                const float* r0 = Fc + (size_t)(vy0 ? y0 : 0) * W_;
                const float* r1 = Fc + (size_t)(vy1 ? y1 : 0) * W_;
                float v00 = (vy0 && vx0) ? __ldg(r0 + x0) : 0.f;
                float v01 = (vy0 && vx1) ? __ldg(r0 + x1) : 0.f;
                float v10 = (vy1 && vx0) ? __ldg(r1 + x0) : 0.f;
                float v11 = (vy1 && vx1) ? __ldg(r1 + x1) : 0.f;
                float wx0 = 1.f - fx, wx1 = fx;
                float wy0 = 1.f - fy, wy1 = fy;
                op[j] = wy0 * (wx0 * v00 + wx1 * v01) + wy1 * (wx0 * v10 + wx1 * v11);
            }
            __stcs(reinterpret_cast<float4*>(outp + (size_t)t * CHW_), o);
        }
    }
}

// ---------------------------------------------------------------------------
extern "C" void kernel_launch(void* const* d_in, const int* in_sizes, int n_in,
                              void* d_out, int out_size) {
    const float* F  = (const float*)d_in[0];
    const float* w1 = (const float*)d_in[1];
    const float* b1 = (const float*)d_in[2];
    const float* a  = (const float*)d_in[3];
    float* out = (float*)d_out;

    float* out_tail = out + (size_t)T_ * CHW_;

    gap_kernel<<<C_ * 4, 256>>>(F);
    theta_kernel<<<1, 256>>>(w1, b1, a, out_tail);

    const int total = C_ * H_ * W4_;
    const int threads = 256;
    const int blocks = (total + threads - 1) / threads;
    sample_kernel<<<blocks, threads>>>(F, out);
}